// round 1
// baseline (speedup 1.0000x reference)
#include <cuda_runtime.h>

#define Bn 256
#define Tn 128
#define Dn 300
#define Hn 512
#define G4 2048
#define OUTD 200

typedef unsigned long long u64;

// -------- static scratch (no cudaMalloc allowed) --------
// g_X: input-projection buffer [T, B, 4H] per encoder (reused for layer0 then layer1)
__device__ float g_X[2][Tn * Bn * G4];           // 2 x 256MB
__device__ float g_H0[2][Tn * Bn * Hn];          // layer0 hidden history [T,B,H]
__device__ float g_H1[2][Tn * Bn * Hn];          // layer1 hidden history [T,B,H]
__device__ float g_c[2][Bn * Hn];                // cell state (re-zeroed per layer)

// -------- packed f32x2 helpers (FFMA2 path, 2x fp32 rate on sm_103a) --------
__device__ __forceinline__ u64 fma2(u64 a, u64 b, u64 c) {
    u64 d;
    asm("fma.rn.f32x2 %0, %1, %2, %3;" : "=l"(d) : "l"(a), "l"(b), "l"(c));
    return d;
}
__device__ __forceinline__ u64 dup2(float v) {
    u64 d; unsigned r = __float_as_uint(v);
    asm("mov.b64 %0, {%1, %1};" : "=l"(d) : "r"(r));
    return d;
}
__device__ __forceinline__ float2 unpack2(u64 v) {
    unsigned lo, hi;
    asm("mov.b64 {%0, %1}, %2;" : "=r"(lo), "=r"(hi) : "l"(v));
    return make_float2(__uint_as_float(lo), __uint_as_float(hi));
}

// -------- fast-but-accurate activations (2 MUFU per sigmoid, err ~1e-6) --------
__device__ __forceinline__ float fast_ex2(float x) {
    float y; asm("ex2.approx.f32 %0, %1;" : "=f"(y) : "f"(x)); return y;
}
__device__ __forceinline__ float fast_rcp(float x) {
    float y; asm("rcp.approx.f32 %0, %1;" : "=f"(y) : "f"(x)); return y;
}
__device__ __forceinline__ float sigf(float x) {
    return fast_rcp(1.0f + fast_ex2(-1.4426950408889634f * x));
}
__device__ __forceinline__ float tanhfast(float x) {
    return 2.0f * fast_rcp(1.0f + fast_ex2(-2.8853900817779268f * x)) - 1.0f;
}

// -------- zero cell state --------
__global__ void zero_c_kernel() {
    int i = blockIdx.x * blockDim.x + threadIdx.x;
    if (i < 2 * Bn * Hn) (&g_c[0][0])[i] = 0.0f;
}

// ============================================================================
// Input-projection GEMM: Out[orow, n] = bias[n] + sum_k A[r,k] * W[k,n]
// BM=64, BN=128, BK=16, 256 threads, 4x8 micro-tile via f32x2.
// perm=1: orow = (r % T)*B + r/T  (embed rows b*T+t -> [T,B] layout)
// perm=0: orow = r                (g_H0 rows are already t*B+b)
// AL==nullptr => A = g_H0[e] (layer 1)
// ============================================================================
__global__ __launch_bounds__(256) void xproj_kernel(
    const float* __restrict__ AL, const float* __restrict__ AR,
    const float* __restrict__ WL, const float* __restrict__ WR,
    const float* __restrict__ bL, const float* __restrict__ bR,
    int K, int perm)
{
    __shared__ __align__(16) u64   As2[16 * 66];
    __shared__ __align__(16) float Bs[16 * 132];

    const int e = blockIdx.z;
    const float* A    = AL ? (e ? AR : AL) : g_H0[e];
    const float* W    = e ? WR : WL;
    const float* bias = e ? bR : bL;
    float* Out = g_X[e];

    const int m0 = blockIdx.x * 64;
    const int n0 = blockIdx.y * 128;
    const int tid = threadIdx.x;
    const int tx = tid & 15, ty = tid >> 4;

    u64 acc[4][4];
#pragma unroll
    for (int i = 0; i < 4; i++)
#pragma unroll
        for (int p = 0; p < 4; p++) acc[i][p] = 0ull;

    const int lr = tid >> 2, lc = tid & 3;   // A-tile loader: row, k-chunk
    const int bk = tid >> 4, bj = tid & 15;  // B-tile loader: k-row, col-chunk
    const int cB = 8 * bj;

    for (int k0 = 0; k0 < K; k0 += 16) {
        // ---- load A tile (transposed, value-duplicated for f32x2) ----
        float4 av = make_float4(0.f, 0.f, 0.f, 0.f);
        int ka = k0 + 4 * lc;
        if (ka < K) av = *(const float4*)&A[(size_t)(m0 + lr) * K + ka];
        As2[(4 * lc + 0) * 66 + lr] = dup2(av.x);
        As2[(4 * lc + 1) * 66 + lr] = dup2(av.y);
        As2[(4 * lc + 2) * 66 + lr] = dup2(av.z);
        As2[(4 * lc + 3) * 66 + lr] = dup2(av.w);
        // ---- load B tile ----
        int kb = k0 + bk;
        float4 b0 = make_float4(0.f, 0.f, 0.f, 0.f), b1 = b0;
        if (kb < K) {
            const float* wp = &W[(size_t)kb * G4 + n0 + cB];
            b0 = *(const float4*)wp;
            b1 = *(const float4*)(wp + 4);
        }
        *(float4*)&Bs[bk * 132 + cB]     = b0;
        *(float4*)&Bs[bk * 132 + cB + 4] = b1;
        __syncthreads();
        // ---- FFMA2 inner loop ----
#pragma unroll
        for (int kk = 0; kk < 16; kk++) {
            ulonglong2 a01 = *(const ulonglong2*)&As2[kk * 66 + 4 * ty];
            ulonglong2 a23 = *(const ulonglong2*)&As2[kk * 66 + 4 * ty + 2];
            ulonglong2 b01 = *(const ulonglong2*)&Bs[kk * 132 + 8 * tx];
            ulonglong2 b23 = *(const ulonglong2*)&Bs[kk * 132 + 8 * tx + 4];
            u64 aa[4] = {a01.x, a01.y, a23.x, a23.y};
            u64 bb[4] = {b01.x, b01.y, b23.x, b23.y};
#pragma unroll
            for (int i = 0; i < 4; i++)
#pragma unroll
                for (int p = 0; p < 4; p++)
                    acc[i][p] = fma2(aa[i], bb[p], acc[i][p]);
        }
        __syncthreads();
    }

    // ---- epilogue: bias add + permuted store ----
#pragma unroll
    for (int i = 0; i < 4; i++) {
        int r = m0 + 4 * ty + i;
        int orow = perm ? ((r & (Tn - 1)) * Bn + (r >> 7)) : r;
        float* op = &Out[(size_t)orow * G4 + n0 + 8 * tx];
#pragma unroll
        for (int p = 0; p < 4; p++) {
            float2 v = unpack2(acc[i][p]);
            int n = n0 + 8 * tx + 2 * p;
            v.x += bias[n];
            v.y += bias[n + 1];
            *(float2*)(op + 2 * p) = v;
        }
    }
}

// ============================================================================
// LSTM step: z = X[t] + h_{t-1} @ Wh, then fused gate update.
// Grid (4 M-tiles, 16 u-tiles, 2 encoders). CTA covers 64 rows x 32 hidden
// units across ALL 4 gates (cols g*512 + u0 + j), so the cell update is local.
// ============================================================================
__global__ __launch_bounds__(256) void lstm_step_kernel(
    int t, int layer,
    const float* __restrict__ WhL, const float* __restrict__ WhR)
{
    __shared__ __align__(16) union {
        struct { u64 As2[16 * 66]; float Bs[16 * 132]; } tl;
        float z[64 * 128];
    } sm;

    const int e = blockIdx.z;
    float* Hbase = layer ? g_H1[e] : g_H0[e];
    const float* hin = (t == 0) ? nullptr : (Hbase + (size_t)(t - 1) * Bn * Hn);
    float* hout = Hbase + (size_t)t * Bn * Hn;
    const float* X = g_X[e] + (size_t)t * Bn * G4;
    float* cst = g_c[e];
    const float* Wh = e ? WhR : WhL;

    const int m0 = blockIdx.x * 64;
    const int u0 = blockIdx.y * 32;
    const int tid = threadIdx.x;
    const int tx = tid & 15, ty = tid >> 4;

    u64 acc[4][4];
#pragma unroll
    for (int i = 0; i < 4; i++)
#pragma unroll
        for (int p = 0; p < 4; p++) acc[i][p] = 0ull;

    if (hin) {  // t==0: h is zero -> z = X only
        const int lr = tid >> 2, lc = tid & 3;
        const int bk = tid >> 4, bj = tid & 15;
        const int cB = 8 * bj;
        const int g = cB >> 5, jj = cB & 31;
        const int nB = g * 512 + u0 + jj;   // gate-strided column mapping
        for (int k0 = 0; k0 < Hn; k0 += 16) {
            float4 av = *(const float4*)&hin[(size_t)(m0 + lr) * Hn + k0 + 4 * lc];
            sm.tl.As2[(4 * lc + 0) * 66 + lr] = dup2(av.x);
            sm.tl.As2[(4 * lc + 1) * 66 + lr] = dup2(av.y);
            sm.tl.As2[(4 * lc + 2) * 66 + lr] = dup2(av.z);
            sm.tl.As2[(4 * lc + 3) * 66 + lr] = dup2(av.w);
            const float* wp = &Wh[(size_t)(k0 + bk) * G4 + nB];
            *(float4*)&sm.tl.Bs[bk * 132 + cB]     = *(const float4*)wp;
            *(float4*)&sm.tl.Bs[bk * 132 + cB + 4] = *(const float4*)(wp + 4);
            __syncthreads();
#pragma unroll
            for (int kk = 0; kk < 16; kk++) {
                ulonglong2 a01 = *(const ulonglong2*)&sm.tl.As2[kk * 66 + 4 * ty];
                ulonglong2 a23 = *(const ulonglong2*)&sm.tl.As2[kk * 66 + 4 * ty + 2];
                ulonglong2 b01 = *(const ulonglong2*)&sm.tl.Bs[kk * 132 + 8 * tx];
                ulonglong2 b23 = *(const ulonglong2*)&sm.tl.Bs[kk * 132 + 8 * tx + 4];
                u64 aa[4] = {a01.x, a01.y, a23.x, a23.y};
                u64 bb[4] = {b01.x, b01.y, b23.x, b23.y};
#pragma unroll
                for (int i = 0; i < 4; i++)
#pragma unroll
                    for (int p = 0; p < 4; p++)
                        acc[i][p] = fma2(aa[i], bb[p], acc[i][p]);
            }
            __syncthreads();
        }
    }

    // stage z through smem so each thread can gather its 4 gates
#pragma unroll
    for (int i = 0; i < 4; i++)
#pragma unroll
        for (int p = 0; p < 4; p++) {
            float2 v = unpack2(acc[i][p]);
            *(float2*)&sm.z[(4 * ty + i) * 128 + 8 * tx + 2 * p] = v;
        }
    __syncthreads();

    // fused LSTM cell update: 2048 (b,u) pairs per CTA, 8 per thread
#pragma unroll
    for (int q = 0; q < 8; q++) {
        int idx = tid + q * 256;
        int u = idx & 31, row = idx >> 5;
        int b = m0 + row, ug = u0 + u;
        const float* Xb = X + (size_t)b * G4 + ug;
        float zi = sm.z[row * 128 + u]      + Xb[0];
        float zj = sm.z[row * 128 + 32 + u] + Xb[512];
        float zf = sm.z[row * 128 + 64 + u] + Xb[1024];
        float zo = sm.z[row * 128 + 96 + u] + Xb[1536];
        size_t ci = (size_t)b * Hn + ug;
        float cv = cst[ci];
        float cn = cv * sigf(zf + 1.0f) + sigf(zi) * tanhfast(zj);  // forget bias = 1
        float hn = tanhfast(cn) * sigf(zo);
        cst[ci] = cn;
        hout[ci] = hn;
    }
}

// ============================================================================
// Gather last valid timestep per example + final projection [B,1024]@[1024,200]
// ============================================================================
__global__ __launch_bounds__(256) void final_kernel(
    const int* __restrict__ lenL, const int* __restrict__ lenR,
    const float* __restrict__ Wt, float* __restrict__ out)
{
    __shared__ float v[2 * Hn];
    int b = blockIdx.x, tid = threadIdx.x;
    int iL = lenL[b] - 1, iR = lenR[b] - 1;
    const float* hL = &g_H1[0][((size_t)iL * Bn + b) * Hn];
    const float* hR = &g_H1[1][((size_t)iR * Bn + b) * Hn];
    v[tid]       = hL[tid];
    v[256 + tid] = hL[256 + tid];
    v[512 + tid] = hR[tid];
    v[768 + tid] = hR[256 + tid];
    __syncthreads();
    if (tid < OUTD) {
        float acc = 0.0f;
#pragma unroll 8
        for (int k = 0; k < 2 * Hn; k++)
            acc += v[k] * Wt[k * OUTD + tid];
        out[b * OUTD + tid] = acc;
    }
}

// ============================================================================
extern "C" void kernel_launch(void* const* d_in, const int* in_sizes, int n_in,
                              void* d_out, int out_size)
{
    const float* left  = (const float*)d_in[0];
    const float* right = (const float*)d_in[1];
    const int*   lenL  = (const int*)d_in[2];
    const int*   lenR  = (const int*)d_in[3];
    const float* lW0 = (const float*)d_in[4];
    const float* lb0 = (const float*)d_in[5];
    const float* lW1 = (const float*)d_in[6];
    const float* lb1 = (const float*)d_in[7];
    const float* rW0 = (const float*)d_in[8];
    const float* rb0 = (const float*)d_in[9];
    const float* rW1 = (const float*)d_in[10];
    const float* rb1 = (const float*)d_in[11];
    const float* tW  = (const float*)d_in[12];
    float* out = (float*)d_out;

    dim3 gx(512, 16, 2);   // xproj: 32768/64 M-tiles x 2048/128 N-tiles x 2 enc
    dim3 gs(4, 16, 2);     // step:  256/64 x 16 u-tiles x 2 enc

    // ---- layer 0 ----
    zero_c_kernel<<<512, 512>>>();
    xproj_kernel<<<gx, 256>>>(left, right, lW0, rW0, lb0, rb0, Dn, 1);
    for (int t = 0; t < Tn; t++)
        lstm_step_kernel<<<gs, 256>>>(t, 0, lW0 + (size_t)Dn * G4, rW0 + (size_t)Dn * G4);

    // ---- layer 1 ----
    xproj_kernel<<<gx, 256>>>(nullptr, nullptr, lW1, rW1, lb1, rb1, Hn, 0);
    zero_c_kernel<<<512, 512>>>();
    for (int t = 0; t < Tn; t++)
        lstm_step_kernel<<<gs, 256>>>(t, 1, lW1 + (size_t)Hn * G4, rW1 + (size_t)Hn * G4);

    // ---- gather + output projection ----
    final_kernel<<<256, 256>>>(lenL, lenR, tW, out);
}

// round 2
// speedup vs baseline: 1.1305x; 1.1305x over previous
#include <cuda_runtime.h>

#define Bn 256
#define Tn 128
#define Dn 300
#define Hn 512
#define G4 2048
#define OUTD 200

typedef unsigned long long u64;

// -------- static scratch (no cudaMalloc allowed) --------
__device__ float g_X[2][Tn * Bn * G4];        // input projections [t][b][2048]
__device__ float g_H0t[2][Tn * Hn * Bn];      // layer0 h history TRANSPOSED [t][unit][b]
__device__ float g_H1t[2][Tn * Hn * Bn];      // layer1 h history TRANSPOSED
__device__ int g_cnt;                          // grid barrier state (zero-init)
__device__ int g_gen;

// -------- packed f32x2 helpers --------
__device__ __forceinline__ u64 fma2(u64 a, u64 b, u64 c) {
    u64 d;
    asm("fma.rn.f32x2 %0, %1, %2, %3;" : "=l"(d) : "l"(a), "l"(b), "l"(c));
    return d;
}
__device__ __forceinline__ u64 dup2(float v) {
    u64 d; unsigned r = __float_as_uint(v);
    asm("mov.b64 %0, {%1, %1};" : "=l"(d) : "r"(r));
    return d;
}
__device__ __forceinline__ float2 unpack2(u64 v) {
    unsigned lo, hi;
    asm("mov.b64 {%0, %1}, %2;" : "=r"(lo), "=r"(hi) : "l"(v));
    return make_float2(__uint_as_float(lo), __uint_as_float(hi));
}

// -------- fast activations --------
__device__ __forceinline__ float fast_ex2(float x) {
    float y; asm("ex2.approx.f32 %0, %1;" : "=f"(y) : "f"(x)); return y;
}
__device__ __forceinline__ float fast_rcp(float x) {
    float y; asm("rcp.approx.f32 %0, %1;" : "=f"(y) : "f"(x)); return y;
}
__device__ __forceinline__ float sigf(float x) {
    return fast_rcp(1.0f + fast_ex2(-1.4426950408889634f * x));
}
__device__ __forceinline__ float tanhfast(float x) {
    return 2.0f * fast_rcp(1.0f + fast_ex2(-2.8853900817779268f * x)) - 1.0f;
}

// ============================================================================
// Input-projection GEMM: X[r, n] = bias[n] + sum_k A[r,k] * W[k,n]
// Rows are t-major: r = t*256 + b (matches g_X [t][b][n] layout).
// mode 0: A = embed [b][t][D]  (layer 0)
// mode 1: A = g_H0t [t][k][b]  (layer 1, k-major -> load contiguous along b)
// ============================================================================
__global__ __launch_bounds__(256) void xproj_kernel(
    const float* __restrict__ AL, const float* __restrict__ AR,
    const float* __restrict__ WL, const float* __restrict__ WR,
    const float* __restrict__ bL, const float* __restrict__ bR,
    int K, int mode)
{
    __shared__ __align__(16) u64   As2[16 * 66];
    __shared__ __align__(16) float Bs[16 * 132];

    const int e = blockIdx.z;
    const float* A    = mode ? g_H0t[e] : (e ? AR : AL);
    const float* W    = e ? WR : WL;
    const float* bias = e ? bR : bL;
    float* Out = g_X[e];

    const int m0 = blockIdx.x * 64;    // rows r = t*256+b; tiles never cross t
    const int n0 = blockIdx.y * 128;
    const int tid = threadIdx.x;
    const int tx = tid & 15, ty = tid >> 4;

    u64 acc[4][4];
#pragma unroll
    for (int i = 0; i < 4; i++)
#pragma unroll
        for (int p = 0; p < 4; p++) acc[i][p] = 0ull;

    const int bk = tid >> 4, bj = tid & 15;  // B-tile loader
    const int cB = 8 * bj;
    const int t0 = m0 >> 8, b0 = m0 & 255;

    for (int k0 = 0; k0 < K; k0 += 16) {
        // ---- load A tile (transposed to [k][row], value-duplicated) ----
        if (mode == 0) {
            const int lr = tid >> 2, lc = tid & 3;
            float4 av = make_float4(0.f, 0.f, 0.f, 0.f);
            int ka = k0 + 4 * lc;
            int r = m0 + lr;                  // t = r>>8, b = r&255
            if (ka < K)
                av = *(const float4*)&A[(size_t)((r & 255) * Tn + (r >> 8)) * K + ka];
            As2[(4 * lc + 0) * 66 + lr] = dup2(av.x);
            As2[(4 * lc + 1) * 66 + lr] = dup2(av.y);
            As2[(4 * lc + 2) * 66 + lr] = dup2(av.z);
            As2[(4 * lc + 3) * 66 + lr] = dup2(av.w);
        } else {
            const int kk = tid >> 4, bb = tid & 15;   // 16 k-rows x 16 b-chunks
            float4 av = *(const float4*)&A[((size_t)t0 * Hn + k0 + kk) * Bn + b0 + 4 * bb];
            As2[kk * 66 + 4 * bb + 0] = dup2(av.x);
            As2[kk * 66 + 4 * bb + 1] = dup2(av.y);
            As2[kk * 66 + 4 * bb + 2] = dup2(av.z);
            As2[kk * 66 + 4 * bb + 3] = dup2(av.w);
        }
        // ---- load B tile ----
        int kb = k0 + bk;
        float4 w0 = make_float4(0.f, 0.f, 0.f, 0.f), w1 = w0;
        if (kb < K) {
            const float* wp = &W[(size_t)kb * G4 + n0 + cB];
            w0 = *(const float4*)wp;
            w1 = *(const float4*)(wp + 4);
        }
        *(float4*)&Bs[bk * 132 + cB]     = w0;
        *(float4*)&Bs[bk * 132 + cB + 4] = w1;
        __syncthreads();
        // ---- FFMA2 inner loop ----
#pragma unroll
        for (int kk = 0; kk < 16; kk++) {
            ulonglong2 a01 = *(const ulonglong2*)&As2[kk * 66 + 4 * ty];
            ulonglong2 a23 = *(const ulonglong2*)&As2[kk * 66 + 4 * ty + 2];
            ulonglong2 b01 = *(const ulonglong2*)&Bs[kk * 132 + 8 * tx];
            ulonglong2 b23 = *(const ulonglong2*)&Bs[kk * 132 + 8 * tx + 4];
            u64 aa[4] = {a01.x, a01.y, a23.x, a23.y};
            u64 bb2[4] = {b01.x, b01.y, b23.x, b23.y};
#pragma unroll
            for (int i = 0; i < 4; i++)
#pragma unroll
                for (int p = 0; p < 4; p++)
                    acc[i][p] = fma2(aa[i], bb2[p], acc[i][p]);
        }
        __syncthreads();
    }

    // ---- epilogue: bias add, store row-major (r = t*256+b == X[t][b]) ----
#pragma unroll
    for (int i = 0; i < 4; i++) {
        int r = m0 + 4 * ty + i;
        float* op = &Out[(size_t)r * G4 + n0 + 8 * tx];
#pragma unroll
        for (int p = 0; p < 4; p++) {
            float2 v = unpack2(acc[i][p]);
            int n = n0 + 8 * tx + 2 * p;
            v.x += bias[n];
            v.y += bias[n + 1];
            *(float2*)(op + 2 * p) = v;
        }
    }
}

// ============================================================================
// Persistent recurrent kernel: one launch per layer, all 128 timesteps.
// 128 CTAs (64 per encoder), 1/SM, co-resident -> software grid barrier.
// Each CTA owns 8 hidden units (x4 gates = 32 W columns) with the weight
// slice resident (pre-duplicated) in SMEM; cell state lives in registers.
// ============================================================================
#define WS_U64   (512 * 32)
#define WS_BYTES (WS_U64 * 8)              // 131072
#define ZS_PITCH 33
#define SMEM_DYN (WS_BYTES + 256 * ZS_PITCH * 4)   // 164864

__global__ __launch_bounds__(256, 1) void lstm_persist(
    const float* __restrict__ WhL, const float* __restrict__ WhR, int layer)
{
    extern __shared__ char smraw[];
    u64*   Ws2  = (u64*)smraw;                    // [512][32] duplicated weights
    float* hbuf = (float*)(smraw + WS_BYTES);     // [32][256] h chunk (GEMM phase)
    float* zs   = (float*)(smraw + WS_BYTES);     // [256][33] gate pre-acts (aliased)

    const int tid = threadIdx.x;
    const int e = blockIdx.x >> 6;
    const int s = blockIdx.x & 63;                // unit slice: units s*8..s*8+7
    const float* Wh = e ? WhR : WhL;
    const float* X  = g_X[e];
    float* Ht = layer ? g_H1t[e] : g_H0t[e];

    // ---- load weight slice, duplicated for f32x2 (once per layer) ----
#pragma unroll 4
    for (int q = 0; q < 64; q++) {
        int idx = tid + 256 * q;
        int k = idx >> 5, c = idx & 31;           // c = g*8 + j
        int col = ((c >> 3) << 9) + s * 8 + (c & 7);
        Ws2[idx] = dup2(Wh[(size_t)k * G4 + col]);
    }

    const int tx = tid & 7, ty = tid >> 3;        // GEMM: 8 col-groups x 32 rp-groups
    const int ua = tid & 7,  ba = tid >> 3;       // phase A: u minor (coalesced X)
    const int ub = tid >> 5, bb = tid & 31;       // phase B: b minor (coalesced h/zs)

    float creg[8];                                 // cell state: (ub, bb+32q)
#pragma unroll
    for (int i = 0; i < 8; i++) creg[i] = 0.0f;

    __syncthreads();

    for (int t = 0; t < Tn; t++) {
        if (t > 0) {
            u64 acc[4][4];
#pragma unroll
            for (int i = 0; i < 4; i++)
#pragma unroll
                for (int j = 0; j < 4; j++) acc[i][j] = 0ull;

            const float4* hsrc = (const float4*)(Ht + (size_t)(t - 1) * Hn * Bn);
            float4 pf[8];
#pragma unroll
            for (int i = 0; i < 8; i++) pf[i] = hsrc[i * 256 + tid];   // chunk 0

            for (int j = 0; j < 16; j++) {
                __syncthreads();                       // hbuf free
#pragma unroll
                for (int i = 0; i < 8; i++)
                    ((float4*)hbuf)[i * 256 + tid] = pf[i];
                if (j < 15) {
                    const float4* src = hsrc + (size_t)(j + 1) * 2048;
#pragma unroll
                    for (int i = 0; i < 8; i++) pf[i] = src[i * 256 + tid];
                }
                __syncthreads();                       // hbuf ready
                const u64* hs2 = (const u64*)hbuf;     // [32][128] natural b-pairs
                const u64* wk  = Ws2 + (size_t)j * 32 * 32;
#pragma unroll
                for (int kk = 0; kk < 32; kk++) {
                    ulonglong2 h01 = *(const ulonglong2*)&hs2[kk * 128 + 4 * ty];
                    ulonglong2 h23 = *(const ulonglong2*)&hs2[kk * 128 + 4 * ty + 2];
                    ulonglong2 w01 = *(const ulonglong2*)&wk[kk * 32 + 4 * tx];
                    ulonglong2 w23 = *(const ulonglong2*)&wk[kk * 32 + 4 * tx + 2];
                    u64 hh[4] = {h01.x, h01.y, h23.x, h23.y};
                    u64 ww[4] = {w01.x, w01.y, w23.x, w23.y};
#pragma unroll
                    for (int i = 0; i < 4; i++)
#pragma unroll
                        for (int jj = 0; jj < 4; jj++)
                            acc[i][jj] = fma2(hh[i], ww[jj], acc[i][jj]);
                }
            }
            __syncthreads();              // hbuf done; region becomes zs
            // ---- epilogue: acc -> zs[row][col] ----
#pragma unroll
            for (int i = 0; i < 4; i++) {
                int r0 = 8 * ty + 2 * i;
#pragma unroll
                for (int jj = 0; jj < 4; jj++) {
                    float2 v = unpack2(acc[i][jj]);
                    int c = 4 * tx + jj;
                    zs[r0 * ZS_PITCH + c]       = v.x;
                    zs[(r0 + 1) * ZS_PITCH + c] = v.y;
                }
            }
        }
        __syncthreads();

        // ---- phase A: zs = (t ? zs : 0) + X[t]  (u-minor: coalesced X) ----
        {
            const float* Xt = X + (size_t)t * Bn * G4 + s * 8 + ua;
#pragma unroll
            for (int q = 0; q < 8; q++) {
                int b = ba + 32 * q;
                const float* Xb = Xt + (size_t)b * G4;
#pragma unroll
                for (int g = 0; g < 4; g++) {
                    float xv = Xb[g * 512];
                    int zi = b * ZS_PITCH + g * 8 + ua;
                    zs[zi] = (t > 0) ? (zs[zi] + xv) : xv;
                }
            }
        }
        __syncthreads();

        // ---- phase B: cell update (b-minor: coalesced h store) ----
        {
            float* hdst = Ht + (size_t)t * Hn * Bn + (size_t)(s * 8 + ub) * Bn;
#pragma unroll
            for (int q = 0; q < 8; q++) {
                int b = bb + 32 * q;
                float zi = zs[b * ZS_PITCH + ub];
                float zj = zs[b * ZS_PITCH + 8 + ub];
                float zf = zs[b * ZS_PITCH + 16 + ub];
                float zo = zs[b * ZS_PITCH + 24 + ub];
                float cn = creg[q] * sigf(zf + 1.0f) + sigf(zi) * tanhfast(zj);
                creg[q] = cn;
                hdst[b] = tanhfast(cn) * sigf(zo);
            }
        }

        // ---- grid barrier (all 128 CTAs co-resident) ----
        __threadfence();
        __syncthreads();
        if (tid == 0) {
            int g = *((volatile int*)&g_gen);
            if (atomicAdd(&g_cnt, 1) == 127) {
                g_cnt = 0;
                __threadfence();
                atomicAdd(&g_gen, 1);
            } else {
                while (*((volatile int*)&g_gen) == g) { }
            }
        }
        __syncthreads();
    }
}

// ============================================================================
// Gather last valid timestep + final projection [B,1024]@[1024,200]
// ============================================================================
__global__ __launch_bounds__(256) void final_kernel(
    const int* __restrict__ lenL, const int* __restrict__ lenR,
    const float* __restrict__ Wt, float* __restrict__ out)
{
    __shared__ float v[2 * Hn];
    int b = blockIdx.x, tid = threadIdx.x;
    int iL = lenL[b] - 1, iR = lenR[b] - 1;
    const float* hL = &g_H1t[0][(size_t)iL * Hn * Bn + b];
    const float* hR = &g_H1t[1][(size_t)iR * Hn * Bn + b];
    v[tid]       = hL[(size_t)tid * Bn];
    v[256 + tid] = hL[(size_t)(256 + tid) * Bn];
    v[512 + tid] = hR[(size_t)tid * Bn];
    v[768 + tid] = hR[(size_t)(256 + tid) * Bn];
    __syncthreads();
    if (tid < OUTD) {
        float acc = 0.0f;
#pragma unroll 8
        for (int k = 0; k < 2 * Hn; k++)
            acc += v[k] * Wt[k * OUTD + tid];
        out[b * OUTD + tid] = acc;
    }
}

// ============================================================================
extern "C" void kernel_launch(void* const* d_in, const int* in_sizes, int n_in,
                              void* d_out, int out_size)
{
    const float* left  = (const float*)d_in[0];
    const float* right = (const float*)d_in[1];
    const int*   lenL  = (const int*)d_in[2];
    const int*   lenR  = (const int*)d_in[3];
    const float* lW0 = (const float*)d_in[4];
    const float* lb0 = (const float*)d_in[5];
    const float* lW1 = (const float*)d_in[6];
    const float* lb1 = (const float*)d_in[7];
    const float* rW0 = (const float*)d_in[8];
    const float* rb0 = (const float*)d_in[9];
    const float* rW1 = (const float*)d_in[10];
    const float* rb1 = (const float*)d_in[11];
    const float* tW  = (const float*)d_in[12];
    float* out = (float*)d_out;

    cudaFuncSetAttribute(lstm_persist,
                         cudaFuncAttributeMaxDynamicSharedMemorySize, SMEM_DYN);

    dim3 gx(512, 16, 2);   // xproj: 32768/64 x 2048/128 x 2 encoders

    // layer 0
    xproj_kernel<<<gx, 256>>>(left, right, lW0, rW0, lb0, rb0, Dn, 0);
    lstm_persist<<<128, 256, SMEM_DYN>>>(lW0 + (size_t)Dn * G4,
                                         rW0 + (size_t)Dn * G4, 0);
    // layer 1
    xproj_kernel<<<gx, 256>>>(nullptr, nullptr, lW1, rW1, lb1, rb1, Hn, 1);
    lstm_persist<<<128, 256, SMEM_DYN>>>(lW1 + (size_t)Hn * G4,
                                         rW1 + (size_t)Hn * G4, 1);
    // gather + output projection
    final_kernel<<<256, 256>>>(lenL, lenR, tW, out);
}

// round 5
// speedup vs baseline: 1.9330x; 1.7098x over previous
#include <cuda_runtime.h>
#include <cstdint>

#define Bn 256
#define Tn 128
#define Dn 300
#define Hn 512
#define G4 2048
#define OUTD 200

typedef unsigned long long u64;

// -------- static scratch --------
__device__ float g_X[2][Tn * Bn * G4];        // input projections [t][b][2048]
__device__ float g_H0[2][Tn * Bn * Hn];       // layer0 h row-major (xproj input)
__device__ float g_H1[2][Tn * Bn * Hn];       // layer1 h row-major (final gather)
// pair-layout h images for MMA staging, tf32-pre-rounded:
// [layer][enc][t][mhalf][row*256 + kcg*4 + l4] float2 = {h[k], h[k+4]}
__device__ float2 g_Hp[2][2][Tn][2][128 * 256];
__device__ int g_cnt;                          // grid barrier (zero-init)
__device__ int g_gen;

// -------- tf32 / mma helpers --------
__device__ __forceinline__ uint32_t cvt_tf32(float f) {
    uint32_t r;
    asm("cvt.rna.tf32.f32 %0, %1;" : "=r"(r) : "f"(f));
    return r;
}
__device__ __forceinline__ void mma8(float* d, uint32_t a0, uint32_t a1,
                                     uint32_t a2, uint32_t a3,
                                     uint32_t b0, uint32_t b1) {
    asm volatile(
        "mma.sync.aligned.m16n8k8.row.col.f32.tf32.tf32.f32 "
        "{%0,%1,%2,%3}, {%4,%5,%6,%7}, {%8,%9}, {%0,%1,%2,%3};"
        : "+f"(d[0]), "+f"(d[1]), "+f"(d[2]), "+f"(d[3])
        : "r"(a0), "r"(a1), "r"(a2), "r"(a3), "r"(b0), "r"(b1));
}

// -------- packed f32x2 helpers (xproj fp32 path) --------
__device__ __forceinline__ u64 fma2(u64 a, u64 b, u64 c) {
    u64 d;
    asm("fma.rn.f32x2 %0, %1, %2, %3;" : "=l"(d) : "l"(a), "l"(b), "l"(c));
    return d;
}
__device__ __forceinline__ u64 dup2(float v) {
    u64 d; unsigned r = __float_as_uint(v);
    asm("mov.b64 %0, {%1, %1};" : "=l"(d) : "r"(r));
    return d;
}
__device__ __forceinline__ float2 unpack2(u64 v) {
    unsigned lo, hi;
    asm("mov.b64 {%0, %1}, %2;" : "=r"(lo), "=r"(hi) : "l"(v));
    return make_float2(__uint_as_float(lo), __uint_as_float(hi));
}

// -------- fast activations --------
__device__ __forceinline__ float fast_ex2(float x) {
    float y; asm("ex2.approx.f32 %0, %1;" : "=f"(y) : "f"(x)); return y;
}
__device__ __forceinline__ float fast_rcp(float x) {
    float y; asm("rcp.approx.f32 %0, %1;" : "=f"(y) : "f"(x)); return y;
}
__device__ __forceinline__ float sigf(float x) {
    return fast_rcp(1.0f + fast_ex2(-1.4426950408889634f * x));
}
__device__ __forceinline__ float tanhfast(float x) {
    return 2.0f * fast_rcp(1.0f + fast_ex2(-2.8853900817779268f * x)) - 1.0f;
}

// ============================================================================
// Input-projection GEMM (fp32 FFMA2): X[r,n] = bias[n] + sum_k A[r,k]*W[k,n]
// r = t*256 + b. mode 0: A = embed [b][t][D]. mode 1: A row-major [r][512].
// ============================================================================
__global__ __launch_bounds__(256) void xproj_kernel(
    const float* __restrict__ AL, const float* __restrict__ AR,
    const float* __restrict__ WL, const float* __restrict__ WR,
    const float* __restrict__ bL, const float* __restrict__ bR,
    int K, int mode)
{
    __shared__ __align__(16) u64   As2[16 * 66];
    __shared__ __align__(16) float Bs[16 * 132];

    const int e = blockIdx.z;
    const float* A    = mode ? g_H0[e] : (e ? AR : AL);
    const float* W    = e ? WR : WL;
    const float* bias = e ? bR : bL;
    float* Out = g_X[e];

    const int m0 = blockIdx.x * 64;
    const int n0 = blockIdx.y * 128;
    const int tid = threadIdx.x;
    const int tx = tid & 15, ty = tid >> 4;

    u64 acc[4][4];
#pragma unroll
    for (int i = 0; i < 4; i++)
#pragma unroll
        for (int p = 0; p < 4; p++) acc[i][p] = 0ull;

    const int lr = tid >> 2, lc = tid & 3;
    const int bk = tid >> 4, bj = tid & 15;
    const int cB = 8 * bj;

    for (int k0 = 0; k0 < K; k0 += 16) {
        float4 av = make_float4(0.f, 0.f, 0.f, 0.f);
        int ka = k0 + 4 * lc;
        int r = m0 + lr;
        if (ka < K) {
            size_t arow = mode ? (size_t)r * K
                               : (size_t)((r & 255) * Tn + (r >> 8)) * K;
            av = *(const float4*)&A[arow + ka];
        }
        As2[(4 * lc + 0) * 66 + lr] = dup2(av.x);
        As2[(4 * lc + 1) * 66 + lr] = dup2(av.y);
        As2[(4 * lc + 2) * 66 + lr] = dup2(av.z);
        As2[(4 * lc + 3) * 66 + lr] = dup2(av.w);
        int kb = k0 + bk;
        float4 w0 = make_float4(0.f, 0.f, 0.f, 0.f), w1 = w0;
        if (kb < K) {
            const float* wp = &W[(size_t)kb * G4 + n0 + cB];
            w0 = *(const float4*)wp;
            w1 = *(const float4*)(wp + 4);
        }
        *(float4*)&Bs[bk * 132 + cB]     = w0;
        *(float4*)&Bs[bk * 132 + cB + 4] = w1;
        __syncthreads();
#pragma unroll
        for (int kk = 0; kk < 16; kk++) {
            ulonglong2 a01 = *(const ulonglong2*)&As2[kk * 66 + 4 * ty];
            ulonglong2 a23 = *(const ulonglong2*)&As2[kk * 66 + 4 * ty + 2];
            ulonglong2 b01 = *(const ulonglong2*)&Bs[kk * 132 + 8 * tx];
            ulonglong2 b23 = *(const ulonglong2*)&Bs[kk * 132 + 8 * tx + 4];
            u64 aa[4] = {a01.x, a01.y, a23.x, a23.y};
            u64 bb2[4] = {b01.x, b01.y, b23.x, b23.y};
#pragma unroll
            for (int i = 0; i < 4; i++)
#pragma unroll
                for (int p = 0; p < 4; p++)
                    acc[i][p] = fma2(aa[i], bb2[p], acc[i][p]);
        }
        __syncthreads();
    }
#pragma unroll
    for (int i = 0; i < 4; i++) {
        int r = m0 + 4 * ty + i;
        float* op = &Out[(size_t)r * G4 + n0 + 8 * tx];
#pragma unroll
        for (int p = 0; p < 4; p++) {
            float2 v = unpack2(acc[i][p]);
            int n = n0 + 8 * tx + 2 * p;
            v.x += bias[n];
            v.y += bias[n + 1];
            *(float2*)(op + 2 * p) = v;
        }
    }
}

// ============================================================================
// Persistent tf32 mma.sync LSTM layer. 128 CTAs = e(2) x m(2) x s(32).
// CTA: M=128 batch x N=64 (16 units x 4 gates) x K=512 per step.
// W fragments resident in smem (mma B-reg order); h streamed in K=64 chunks
// (double-buffered) from a pair-layout global image; cell state in registers.
// ============================================================================
#define WB_BYTES  131072                      // 64 ksteps x 8 nt x 32 lanes x f2
#define AS2_F2PAD 36                          // padded row stride (f2 units)
#define AS2_BYTES (128 * AS2_F2PAD * 8)       // 36864
#define SMEM_DYN  (WB_BYTES + 2 * AS2_BYTES)  // 204800

__global__ __launch_bounds__(256, 1) void lstm_persist_mma(
    const float* __restrict__ WhL, const float* __restrict__ WhR, int layer)
{
    extern __shared__ __align__(16) char sm[];
    float2* WB = (float2*)sm;
    float2* Ab0 = (float2*)(sm + WB_BYTES);
    float2* Ab1 = (float2*)(sm + WB_BYTES + AS2_BYTES);
    float*  zs  = (float*)(sm + WB_BYTES);    // aliases Ab0 (used post-GEMM)

    const int tid = threadIdx.x, lane = tid & 31, wid = tid >> 5;
    const int wm = wid >> 1, wn = wid & 1;    // 4x2 warp grid
    const int gid = lane >> 2, tig = lane & 3;
    const int e = blockIdx.x >> 6;
    const int m = (blockIdx.x >> 5) & 1;
    const int s = blockIdx.x & 31;
    const int m0 = m * 128, u0 = s * 16;

    const float* Wh = e ? WhR : WhL;
    const float* X  = g_X[e];
    float* Hrow = (layer ? g_H1[e] : g_H0[e]);

    // ---- precompute W fragments in mma B-register order (tf32) ----
#pragma unroll 4
    for (int i = 0; i < 64; i++) {
        int idx = tid + 256 * i;              // 0..16383
        int ln = idx & 31, nt = (idx >> 5) & 7, ks = idx >> 8;
        int n = nt * 8 + (ln >> 2);
        int k = ks * 8 + (ln & 3);
        int col = ((n >> 4) << 9) + u0 + (n & 15);
        uint32_t b0 = cvt_tf32(Wh[(size_t)k * G4 + col]);
        uint32_t b1 = cvt_tf32(Wh[(size_t)(k + 4) * G4 + col]);
        WB[idx] = make_float2(__uint_as_float(b0), __uint_as_float(b1));
    }

    float creg[8];
#pragma unroll
    for (int i = 0; i < 8; i++) creg[i] = 0.0f;
    const int eu = tid & 15, erg = tid >> 4;

    __syncthreads();

    for (int t = 0; t < Tn; t++) {
        if (t > 0) {
            float d[2][4][4];
#pragma unroll
            for (int a = 0; a < 2; a++)
#pragma unroll
                for (int b = 0; b < 4; b++)
#pragma unroll
                    for (int c = 0; c < 4; c++) d[a][b][c] = 0.0f;

            const float4* himg = (const float4*)&g_Hp[layer][e][t - 1][m][0];
            float4 stg[8];
            // prologue: chunk 0 (f4 row stride = 128, chunk = 16 f4/row)
#pragma unroll
            for (int i = 0; i < 8; i++) {
                int row = (tid >> 4) + 16 * i, c = tid & 15;
                stg[i] = himg[(size_t)row * 128 + c];
            }
#pragma unroll
            for (int i = 0; i < 8; i++) {
                int row = (tid >> 4) + 16 * i, c = tid & 15;
                ((float4*)Ab0)[row * 18 + c] = stg[i];
            }
            __syncthreads();

            for (int kc = 0; kc < 8; kc++) {
                if (kc < 7) {
#pragma unroll
                    for (int i = 0; i < 8; i++) {
                        int row = (tid >> 4) + 16 * i, c = tid & 15;
                        stg[i] = himg[(size_t)row * 128 + (kc + 1) * 16 + c];
                    }
                }
                const float2* A2 = (kc & 1) ? Ab1 : Ab0;
#pragma unroll
                for (int k8 = 0; k8 < 8; k8++) {
                    uint2 bf[4];
                    const float2* wbp = WB + ((size_t)(kc * 8 + k8) * 8 + wn * 4) * 32 + lane;
#pragma unroll
                    for (int j = 0; j < 4; j++) bf[j] = *(const uint2*)&wbp[j * 32];
#pragma unroll
                    for (int ms = 0; ms < 2; ms++) {
                        int R = wm * 32 + ms * 16;
                        uint2 alo = *(const uint2*)&A2[(R + gid) * AS2_F2PAD + k8 * 4 + tig];
                        uint2 ahi = *(const uint2*)&A2[(R + 8 + gid) * AS2_F2PAD + k8 * 4 + tig];
#pragma unroll
                        for (int j = 0; j < 4; j++)
                            mma8(d[ms][j], alo.x, ahi.x, alo.y, ahi.y,
                                 bf[j].x, bf[j].y);
                    }
                }
                if (kc < 7) {
                    __syncthreads();
                    float2* Aw = (kc & 1) ? Ab0 : Ab1;
#pragma unroll
                    for (int i = 0; i < 8; i++) {
                        int row = (tid >> 4) + 16 * i, c = tid & 15;
                        ((float4*)Aw)[row * 18 + c] = stg[i];
                    }
                    __syncthreads();
                }
            }
            __syncthreads();
            // ---- d -> zs[row][64] (pitch 66) ----
#pragma unroll
            for (int ms = 0; ms < 2; ms++) {
                int r0 = wm * 32 + ms * 16 + gid;
#pragma unroll
                for (int j = 0; j < 4; j++) {
                    int c = wn * 32 + j * 8 + tig * 2;
                    *(float2*)&zs[r0 * 66 + c] =
                        make_float2(d[ms][j][0], d[ms][j][1]);
                    *(float2*)&zs[(r0 + 8) * 66 + c] =
                        make_float2(d[ms][j][2], d[ms][j][3]);
                }
            }
            __syncthreads();
        }

        // ---- epilogue: X add + cell update + dual h store ----
        {
            float* hw = (float*)&g_Hp[layer][e][t][m][0];
            float* hr = Hrow + ((size_t)t * Bn + m0) * Hn + u0;
            const float* Xt = X + ((size_t)t * Bn + m0) * G4 + u0;
            int pofs = s * 16 + ((eu >> 3) << 3) + ((eu & 3) << 1) + ((eu >> 2) & 1);
#pragma unroll
            for (int q = 0; q < 8; q++) {
                int row = erg + 16 * q;
                const float* Xb = Xt + (size_t)row * G4;
                float zi = Xb[eu], zj = Xb[512 + eu];
                float zf = Xb[1024 + eu], zo = Xb[1536 + eu];
                if (t > 0) {
                    zi += zs[row * 66 + eu];
                    zj += zs[row * 66 + 16 + eu];
                    zf += zs[row * 66 + 32 + eu];
                    zo += zs[row * 66 + 48 + eu];
                }
                float cn = creg[q] * sigf(zf + 1.0f) + sigf(zi) * tanhfast(zj);
                creg[q] = cn;
                float hv = tanhfast(cn) * sigf(zo);
                hr[(size_t)row * Hn + eu] = hv;                      // fp32 row-major
                hw[row * 512 + pofs] = __uint_as_float(cvt_tf32(hv)); // tf32 pair image
            }
        }

        // ---- grid barrier ----
        if (t != Tn - 1) {
            __threadfence();
            __syncthreads();
            if (tid == 0) {
                int g = *((volatile int*)&g_gen);
                if (atomicAdd(&g_cnt, 1) == 127) {
                    g_cnt = 0;
                    __threadfence();
                    atomicAdd(&g_gen, 1);
                } else {
                    while (*((volatile int*)&g_gen) == g) { }
                }
            }
            __syncthreads();
        }
    }
}

// ============================================================================
// Gather last valid timestep + final projection [B,1024]@[1024,200]
// ============================================================================
__global__ __launch_bounds__(256) void final_kernel(
    const int* __restrict__ lenL, const int* __restrict__ lenR,
    const float* __restrict__ Wt, float* __restrict__ out)
{
    __shared__ float v[2 * Hn];
    int b = blockIdx.x, tid = threadIdx.x;
    int iL = lenL[b] - 1, iR = lenR[b] - 1;
    const float* hL = &g_H1[0][((size_t)iL * Bn + b) * Hn];
    const float* hR = &g_H1[1][((size_t)iR * Bn + b) * Hn];
    v[tid]       = hL[tid];
    v[256 + tid] = hL[256 + tid];
    v[512 + tid] = hR[tid];
    v[768 + tid] = hR[256 + tid];
    __syncthreads();
    if (tid < OUTD) {
        float acc = 0.0f;
#pragma unroll 8
        for (int k = 0; k < 2 * Hn; k++)
            acc += v[k] * Wt[k * OUTD + tid];
        out[b * OUTD + tid] = acc;
    }
}

// ============================================================================
extern "C" void kernel_launch(void* const* d_in, const int* in_sizes, int n_in,
                              void* d_out, int out_size)
{
    const float* left  = (const float*)d_in[0];
    const float* right = (const float*)d_in[1];
    const int*   lenL  = (const int*)d_in[2];
    const int*   lenR  = (const int*)d_in[3];
    const float* lW0 = (const float*)d_in[4];
    const float* lb0 = (const float*)d_in[5];
    const float* lW1 = (const float*)d_in[6];
    const float* lb1 = (const float*)d_in[7];
    const float* rW0 = (const float*)d_in[8];
    const float* rb0 = (const float*)d_in[9];
    const float* rW1 = (const float*)d_in[10];
    const float* rb1 = (const float*)d_in[11];
    const float* tW  = (const float*)d_in[12];
    float* out = (float*)d_out;

    static int smem_set = 0;
    if (!smem_set) {
        cudaFuncSetAttribute(lstm_persist_mma,
                             cudaFuncAttributeMaxDynamicSharedMemorySize, SMEM_DYN);
        smem_set = 1;
    }

    dim3 gx(512, 16, 2);

    // layer 0
    xproj_kernel<<<gx, 256>>>(left, right, lW0, rW0, lb0, rb0, Dn, 0);
    lstm_persist_mma<<<128, 256, SMEM_DYN>>>(lW0 + (size_t)Dn * G4,
                                             rW0 + (size_t)Dn * G4, 0);
    // layer 1
    xproj_kernel<<<gx, 256>>>(nullptr, nullptr, lW1, rW1, lb1, rb1, Hn, 1);
    lstm_persist_mma<<<128, 256, SMEM_DYN>>>(lW1 + (size_t)Hn * G4,
                                             rW1 + (size_t)Hn * G4, 1);
    // gather + output projection
    final_kernel<<<256, 256>>>(lenL, lenR, tW, out);
}

// round 6
// speedup vs baseline: 3.2720x; 1.6927x over previous
#include <cuda_runtime.h>
#include <cstdint>

#define Bn 256
#define Tn 128
#define Dn 300
#define Hn 512
#define G4 2048
#define OUTD 200

typedef unsigned long long u64;

// -------- static scratch --------
__device__ float g_X[2][Tn * Bn * G4];        // input projections [t][b][2048]
__device__ float g_H1[2][Tn * Bn * Hn];       // layer1 h row-major (final gather)
// pair-layout h images, tf32-pre-rounded:
// [layer][enc][t][mhalf][row*256 + k8grp*4 + tig] float2 = {h[k], h[k+4]}
__device__ float2 g_Hp[2][2][Tn][2][128 * 256];
__device__ int g_cnt4[4];                      // per-(e,m) group barriers
__device__ int g_gen4[4];

// -------- tf32 / mma helpers --------
__device__ __forceinline__ uint32_t cvt_tf32(float f) {
    uint32_t r;
    asm("cvt.rna.tf32.f32 %0, %1;" : "=r"(r) : "f"(f));
    return r;
}
__device__ __forceinline__ float tf32f(float f) {
    return __uint_as_float(cvt_tf32(f));
}
__device__ __forceinline__ void mma8(float* d, uint32_t a0, uint32_t a1,
                                     uint32_t a2, uint32_t a3,
                                     uint32_t b0, uint32_t b1) {
    asm volatile(
        "mma.sync.aligned.m16n8k8.row.col.f32.tf32.tf32.f32 "
        "{%0,%1,%2,%3}, {%4,%5,%6,%7}, {%8,%9}, {%0,%1,%2,%3};"
        : "+f"(d[0]), "+f"(d[1]), "+f"(d[2]), "+f"(d[3])
        : "r"(a0), "r"(a1), "r"(a2), "r"(a3), "r"(b0), "r"(b1));
}

// -------- fast activations --------
__device__ __forceinline__ float fast_ex2(float x) {
    float y; asm("ex2.approx.f32 %0, %1;" : "=f"(y) : "f"(x)); return y;
}
__device__ __forceinline__ float fast_rcp(float x) {
    float y; asm("rcp.approx.f32 %0, %1;" : "=f"(y) : "f"(x)); return y;
}
__device__ __forceinline__ float sigf(float x) {
    return fast_rcp(1.0f + fast_ex2(-1.4426950408889634f * x));
}
__device__ __forceinline__ float tanhfast(float x) {
    return 2.0f * fast_rcp(1.0f + fast_ex2(-2.8853900817779268f * x)) - 1.0f;
}

__device__ __forceinline__ float4 gload4(const float* p, int k0, int K) {
    if (k0 + 3 < K) return *(const float4*)p;
    float4 v = make_float4(0.f, 0.f, 0.f, 0.f);
    if (k0 < K)     v.x = p[0];
    if (k0 + 1 < K) v.y = p[1];
    if (k0 + 2 < K) v.z = p[2];
    return v;  // k0+3 >= K always here
}

// ============================================================================
// Input-projection GEMM via tf32 mma.sync.
// X[r,n] = bias[n] + sum_k A[r,k]*W[k,n],  r = t*256+b.
// CTA tile M=128 x N=128, K chunks of 16. 8 warps: wm(2) x wn(4),
// warp tile 64 rows x 32 cols. Fragments staged in smem as tf32 {k,k+4} pairs.
// mode 0: A = embed [b][t][K] (K=300, guarded tail)
// mode 1: A = g_Hp[0][e][t][mh] pair image (K=512, zero conversion)
// ============================================================================
#define XP_PITCH 10   // float2 pitch for pair tiles

__global__ __launch_bounds__(256) void xproj_mma(
    const float* __restrict__ AL, const float* __restrict__ AR,
    const float* __restrict__ WL, const float* __restrict__ WR,
    const float* __restrict__ bL, const float* __restrict__ bR,
    int K, int mode)
{
    __shared__ __align__(16) float2 Apair[128 * XP_PITCH];
    __shared__ __align__(16) float2 Wpair[128 * XP_PITCH];

    const int e = blockIdx.z;
    const float* A    = e ? AR : AL;          // mode 0 only
    const float* W    = e ? WR : WL;
    const float* bias = e ? bR : bL;
    float* Out = g_X[e];

    const int m0 = blockIdx.x * 128;
    const int n0 = blockIdx.y * 128;
    const int tid = threadIdx.x, lane = tid & 31, wid = tid >> 5;
    const int wm = wid & 1, wn = wid >> 1;
    const int gid = lane >> 2, tig = lane & 3;

    const int tt = m0 >> 8, mh = (m0 >> 7) & 1;   // fixed t, mhalf per tile

    float d[4][4][4];
#pragma unroll
    for (int a = 0; a < 4; a++)
#pragma unroll
        for (int b = 0; b < 4; b++)
#pragma unroll
            for (int c = 0; c < 4; c++) d[a][b][c] = 0.0f;

    // staging thread roles
    const int arow = tid >> 1, ag = tid & 1;            // A: row, k8-group
    const int wg = tid >> 7, wtk = (tid >> 5) & 3, wcc = tid & 31;  // W

    const int nk = (K + 15) >> 4;
    for (int kc16 = 0; kc16 < nk; kc16++) {
        const int kc = kc16 * 16;
        __syncthreads();
        // ---- stage A pairs ----
        if (mode == 0) {
            int b = (m0 & 255) + arow;
            const float* ap = A + ((size_t)b * Tn + tt) * K + kc + ag * 8;
            int kb = kc + ag * 8;
            float4 lo = (kb     < K) ? gload4(ap, kb, K)
                                     : make_float4(0.f, 0.f, 0.f, 0.f);
            float4 hi = (kb + 4 < K) ? gload4(ap + 4, kb + 4, K)
                                     : make_float4(0.f, 0.f, 0.f, 0.f);
            float2* dst = &Apair[arow * XP_PITCH + ag * 4];
            dst[0] = make_float2(tf32f(lo.x), tf32f(hi.x));
            dst[1] = make_float2(tf32f(lo.y), tf32f(hi.y));
            dst[2] = make_float2(tf32f(lo.z), tf32f(hi.z));
            dst[3] = make_float2(tf32f(lo.w), tf32f(hi.w));
        } else {
            const float4* src = (const float4*)
                &g_Hp[0][e][tt][mh][(size_t)arow * 256 + ((kc >> 3) + ag) * 4];
            float4 v0 = src[0], v1 = src[1];
            float4* dst = (float4*)&Apair[arow * XP_PITCH + ag * 4];
            dst[0] = v0;
            dst[1] = v1;
        }
        // ---- stage W pairs ----
        {
            int k1 = kc + wg * 8 + wtk, k2 = k1 + 4;
            const float* wp1 = W + (size_t)k1 * G4 + n0 + wcc * 4;
            const float* wp2 = W + (size_t)k2 * G4 + n0 + wcc * 4;
            float4 lo = (k1 < K) ? *(const float4*)wp1
                                 : make_float4(0.f, 0.f, 0.f, 0.f);
            float4 hi = (k2 < K) ? *(const float4*)wp2
                                 : make_float4(0.f, 0.f, 0.f, 0.f);
            int c0 = wcc * 4, pidx = wg * 4 + wtk;
            Wpair[(c0 + 0) * XP_PITCH + pidx] = make_float2(tf32f(lo.x), tf32f(hi.x));
            Wpair[(c0 + 1) * XP_PITCH + pidx] = make_float2(tf32f(lo.y), tf32f(hi.y));
            Wpair[(c0 + 2) * XP_PITCH + pidx] = make_float2(tf32f(lo.z), tf32f(hi.z));
            Wpair[(c0 + 3) * XP_PITCH + pidx] = make_float2(tf32f(lo.w), tf32f(hi.w));
        }
        __syncthreads();
        // ---- compute: 2 k8 groups x 16 MMAs per warp ----
#pragma unroll
        for (int g = 0; g < 2; g++) {
            uint2 bf[4];
#pragma unroll
            for (int j = 0; j < 4; j++) {
                int col = wn * 32 + j * 8 + gid;
                bf[j] = *(const uint2*)&Wpair[col * XP_PITCH + g * 4 + tig];
            }
#pragma unroll
            for (int ms = 0; ms < 4; ms++) {
                int R = wm * 64 + ms * 16;
                uint2 alo = *(const uint2*)&Apair[(R + gid) * XP_PITCH + g * 4 + tig];
                uint2 ahi = *(const uint2*)&Apair[(R + 8 + gid) * XP_PITCH + g * 4 + tig];
#pragma unroll
                for (int j = 0; j < 4; j++)
                    mma8(d[ms][j], alo.x, ahi.x, alo.y, ahi.y, bf[j].x, bf[j].y);
            }
        }
    }

    // ---- epilogue: bias add + store ----
#pragma unroll
    for (int ms = 0; ms < 4; ms++) {
        int r = m0 + wm * 64 + ms * 16 + gid;
#pragma unroll
        for (int j = 0; j < 4; j++) {
            int n = n0 + wn * 32 + j * 8 + tig * 2;
            float2 bv = *(const float2*)&bias[n];
            *(float2*)&Out[(size_t)r * G4 + n] =
                make_float2(d[ms][j][0] + bv.x, d[ms][j][1] + bv.y);
            *(float2*)&Out[(size_t)(r + 8) * G4 + n] =
                make_float2(d[ms][j][2] + bv.x, d[ms][j][3] + bv.y);
        }
    }
}

// ============================================================================
// Persistent tf32 mma.sync LSTM layer. 128 CTAs = e(2) x m(2) x s(32).
// CTA: M=128 batch x N=64 (16 units x 4 gates) x K=512 per step.
// W fragments resident in smem; h streamed in K=64 chunks (double-buffered)
// from pair-layout global image; cell state in registers.
// Per-(e,m) 32-CTA group barriers between steps.
// ============================================================================
#define WB_BYTES  131072
#define AS2_F2PAD 36
#define AS2_BYTES (128 * AS2_F2PAD * 8)
#define SMEM_DYN  (WB_BYTES + 2 * AS2_BYTES)

__global__ __launch_bounds__(256, 1) void lstm_persist_mma(
    const float* __restrict__ WhL, const float* __restrict__ WhR, int layer)
{
    extern __shared__ __align__(16) char sm[];
    float2* WB = (float2*)sm;
    float2* Ab0 = (float2*)(sm + WB_BYTES);
    float2* Ab1 = (float2*)(sm + WB_BYTES + AS2_BYTES);
    float*  zs  = (float*)(sm + WB_BYTES);    // aliases Ab0 (post-GEMM)

    const int tid = threadIdx.x, lane = tid & 31, wid = tid >> 5;
    const int wm = wid >> 1, wn = wid & 1;
    const int gid = lane >> 2, tig = lane & 3;
    const int e = blockIdx.x >> 6;
    const int m = (blockIdx.x >> 5) & 1;
    const int s = blockIdx.x & 31;
    const int grp = blockIdx.x >> 5;          // (e,m) barrier group
    const int m0 = m * 128, u0 = s * 16;

    const float* Wh = e ? WhR : WhL;
    const float* X  = g_X[e];
    float* Hrow = g_H1[e];

    // ---- precompute W fragments in mma B-register order (tf32) ----
#pragma unroll 4
    for (int i = 0; i < 64; i++) {
        int idx = tid + 256 * i;
        int ln = idx & 31, nt = (idx >> 5) & 7, ks = idx >> 8;
        int n = nt * 8 + (ln >> 2);
        int k = ks * 8 + (ln & 3);
        int col = ((n >> 4) << 9) + u0 + (n & 15);
        uint32_t b0 = cvt_tf32(Wh[(size_t)k * G4 + col]);
        uint32_t b1 = cvt_tf32(Wh[(size_t)(k + 4) * G4 + col]);
        WB[idx] = make_float2(__uint_as_float(b0), __uint_as_float(b1));
    }

    float creg[8];
#pragma unroll
    for (int i = 0; i < 8; i++) creg[i] = 0.0f;
    const int eu = tid & 15, erg = tid >> 4;

    __syncthreads();

    for (int t = 0; t < Tn; t++) {
        if (t > 0) {
            float d[2][4][4];
#pragma unroll
            for (int a = 0; a < 2; a++)
#pragma unroll
                for (int b = 0; b < 4; b++)
#pragma unroll
                    for (int c = 0; c < 4; c++) d[a][b][c] = 0.0f;

            const float4* himg = (const float4*)&g_Hp[layer][e][t - 1][m][0];
            float4 stg[8];
#pragma unroll
            for (int i = 0; i < 8; i++) {
                int row = (tid >> 4) + 16 * i, c = tid & 15;
                stg[i] = himg[(size_t)row * 128 + c];
            }
#pragma unroll
            for (int i = 0; i < 8; i++) {
                int row = (tid >> 4) + 16 * i, c = tid & 15;
                ((float4*)Ab0)[row * 18 + c] = stg[i];
            }
            __syncthreads();

            for (int kc = 0; kc < 8; kc++) {
                if (kc < 7) {
#pragma unroll
                    for (int i = 0; i < 8; i++) {
                        int row = (tid >> 4) + 16 * i, c = tid & 15;
                        stg[i] = himg[(size_t)row * 128 + (kc + 1) * 16 + c];
                    }
                }
                const float2* A2 = (kc & 1) ? Ab1 : Ab0;
#pragma unroll
                for (int k8 = 0; k8 < 8; k8++) {
                    uint2 bf[4];
                    const float2* wbp = WB + ((size_t)(kc * 8 + k8) * 8 + wn * 4) * 32 + lane;
#pragma unroll
                    for (int j = 0; j < 4; j++) bf[j] = *(const uint2*)&wbp[j * 32];
#pragma unroll
                    for (int ms = 0; ms < 2; ms++) {
                        int R = wm * 32 + ms * 16;
                        uint2 alo = *(const uint2*)&A2[(R + gid) * AS2_F2PAD + k8 * 4 + tig];
                        uint2 ahi = *(const uint2*)&A2[(R + 8 + gid) * AS2_F2PAD + k8 * 4 + tig];
#pragma unroll
                        for (int j = 0; j < 4; j++)
                            mma8(d[ms][j], alo.x, ahi.x, alo.y, ahi.y,
                                 bf[j].x, bf[j].y);
                    }
                }
                if (kc < 7) {
                    __syncthreads();
                    float2* Aw = (kc & 1) ? Ab0 : Ab1;
#pragma unroll
                    for (int i = 0; i < 8; i++) {
                        int row = (tid >> 4) + 16 * i, c = tid & 15;
                        ((float4*)Aw)[row * 18 + c] = stg[i];
                    }
                    __syncthreads();
                }
            }
            __syncthreads();
#pragma unroll
            for (int ms = 0; ms < 2; ms++) {
                int r0 = wm * 32 + ms * 16 + gid;
#pragma unroll
                for (int j = 0; j < 4; j++) {
                    int c = wn * 32 + j * 8 + tig * 2;
                    *(float2*)&zs[r0 * 66 + c] =
                        make_float2(d[ms][j][0], d[ms][j][1]);
                    *(float2*)&zs[(r0 + 8) * 66 + c] =
                        make_float2(d[ms][j][2], d[ms][j][3]);
                }
            }
            __syncthreads();
        }

        // ---- epilogue: X add + cell update + h store ----
        {
            float* hw = (float*)&g_Hp[layer][e][t][m][0];
            float* hr = Hrow + ((size_t)t * Bn + m0) * Hn + u0;
            const float* Xt = X + ((size_t)t * Bn + m0) * G4 + u0;
            int pofs = s * 16 + ((eu >> 3) << 3) + ((eu & 3) << 1) + ((eu >> 2) & 1);
#pragma unroll
            for (int q = 0; q < 8; q++) {
                int row = erg + 16 * q;
                const float* Xb = Xt + (size_t)row * G4;
                float zi = Xb[eu], zj = Xb[512 + eu];
                float zf = Xb[1024 + eu], zo = Xb[1536 + eu];
                if (t > 0) {
                    zi += zs[row * 66 + eu];
                    zj += zs[row * 66 + 16 + eu];
                    zf += zs[row * 66 + 32 + eu];
                    zo += zs[row * 66 + 48 + eu];
                }
                float cn = creg[q] * sigf(zf + 1.0f) + sigf(zi) * tanhfast(zj);
                creg[q] = cn;
                float hv = tanhfast(cn) * sigf(zo);
                if (layer) hr[(size_t)row * Hn + eu] = hv;            // final gather
                hw[row * 512 + pofs] = __uint_as_float(cvt_tf32(hv)); // pair image
            }
        }

        // ---- per-(e,m) group barrier (32 CTAs) ----
        if (t != Tn - 1) {
            __threadfence();
            __syncthreads();
            if (tid == 0) {
                int g = *((volatile int*)&g_gen4[grp]);
                if (atomicAdd(&g_cnt4[grp], 1) == 31) {
                    g_cnt4[grp] = 0;
                    __threadfence();
                    atomicAdd(&g_gen4[grp], 1);
                } else {
                    while (*((volatile int*)&g_gen4[grp]) == g) { }
                }
            }
            __syncthreads();
        }
    }
}

// ============================================================================
// Gather last valid timestep + final projection [B,1024]@[1024,200]
// ============================================================================
__global__ __launch_bounds__(256) void final_kernel(
    const int* __restrict__ lenL, const int* __restrict__ lenR,
    const float* __restrict__ Wt, float* __restrict__ out)
{
    __shared__ float v[2 * Hn];
    int b = blockIdx.x, tid = threadIdx.x;
    int iL = lenL[b] - 1, iR = lenR[b] - 1;
    const float* hL = &g_H1[0][((size_t)iL * Bn + b) * Hn];
    const float* hR = &g_H1[1][((size_t)iR * Bn + b) * Hn];
    v[tid]       = hL[tid];
    v[256 + tid] = hL[256 + tid];
    v[512 + tid] = hR[tid];
    v[768 + tid] = hR[256 + tid];
    __syncthreads();
    if (tid < OUTD) {
        float acc = 0.0f;
#pragma unroll 8
        for (int k = 0; k < 2 * Hn; k++)
            acc += v[k] * Wt[k * OUTD + tid];
        out[b * OUTD + tid] = acc;
    }
}

// ============================================================================
extern "C" void kernel_launch(void* const* d_in, const int* in_sizes, int n_in,
                              void* d_out, int out_size)
{
    const float* left  = (const float*)d_in[0];
    const float* right = (const float*)d_in[1];
    const int*   lenL  = (const int*)d_in[2];
    const int*   lenR  = (const int*)d_in[3];
    const float* lW0 = (const float*)d_in[4];
    const float* lb0 = (const float*)d_in[5];
    const float* lW1 = (const float*)d_in[6];
    const float* lb1 = (const float*)d_in[7];
    const float* rW0 = (const float*)d_in[8];
    const float* rb0 = (const float*)d_in[9];
    const float* rW1 = (const float*)d_in[10];
    const float* rb1 = (const float*)d_in[11];
    const float* tW  = (const float*)d_in[12];
    float* out = (float*)d_out;

    static int smem_set = 0;
    if (!smem_set) {
        cudaFuncSetAttribute(lstm_persist_mma,
                             cudaFuncAttributeMaxDynamicSharedMemorySize, SMEM_DYN);
        smem_set = 1;
    }

    dim3 gx(256, 16, 2);   // 32768/128 M-tiles x 2048/128 N-tiles x 2 enc

    // layer 0
    xproj_mma<<<gx, 256>>>(left, right, lW0, rW0, lb0, rb0, Dn, 0);
    lstm_persist_mma<<<128, 256, SMEM_DYN>>>(lW0 + (size_t)Dn * G4,
                                             rW0 + (size_t)Dn * G4, 0);
    // layer 1 (reads layer-0 pair image directly)
    xproj_mma<<<gx, 256>>>(nullptr, nullptr, lW1, rW1, lb1, rb1, Hn, 1);
    lstm_persist_mma<<<128, 256, SMEM_DYN>>>(lW1 + (size_t)Hn * G4,
                                             rW1 + (size_t)Hn * G4, 1);
    // gather + output projection
    final_kernel<<<256, 256>>>(lenL, lenR, tW, out);
}